// round 1
// baseline (speedup 1.0000x reference)
#include <cuda_runtime.h>
#include <math.h>

#define EMB 768
#define SEQ 2048
#define BATCH 4
#define NHEAD 12
#define HDIM 64
#define FFDIM 3072
#define MROWS (BATCH*SEQ)   // 8192

// ---------------- scratch (device globals; no allocation allowed) ----------
__device__ float g_xn   [MROWS*EMB];
__device__ float g_q    [MROWS*EMB];
__device__ float g_k    [MROWS*EMB];
__device__ float g_v    [MROWS*EMB];
__device__ float g_gate [MROWS*EMB];
__device__ float g_skip [MROWS*EMB];
__device__ float g_ctx  [MROWS*EMB];
__device__ float g_attno[MROWS*EMB];
__device__ float g_h    [MROWS*EMB];
__device__ float g_hn   [MROWS*EMB];
__device__ float g_ff1  [MROWS*FFDIM];

// ---------------- layernorm: one block per row of 768 ----------------------
__global__ __launch_bounds__(256) void ln_kernel(
    const float* __restrict__ x, const float* __restrict__ w,
    const float* __restrict__ b, float* __restrict__ y)
{
    __shared__ float sh[8];
    int t = threadIdx.x;
    const float* xr = x + (size_t)blockIdx.x * EMB;
    float v0 = xr[t], v1 = xr[t + 256], v2 = xr[t + 512];

    float s = v0 + v1 + v2;
    #pragma unroll
    for (int o = 16; o; o >>= 1) s += __shfl_xor_sync(~0u, s, o);
    if ((t & 31) == 0) sh[t >> 5] = s;
    __syncthreads();
    float mean = (sh[0]+sh[1]+sh[2]+sh[3]+sh[4]+sh[5]+sh[6]+sh[7]) * (1.0f/768.0f);
    __syncthreads();

    float d0 = v0 - mean, d1 = v1 - mean, d2 = v2 - mean;
    float q = d0*d0 + d1*d1 + d2*d2;
    #pragma unroll
    for (int o = 16; o; o >>= 1) q += __shfl_xor_sync(~0u, q, o);
    if ((t & 31) == 0) sh[t >> 5] = q;
    __syncthreads();
    float var = (sh[0]+sh[1]+sh[2]+sh[3]+sh[4]+sh[5]+sh[6]+sh[7]) * (1.0f/768.0f);
    float rstd = rsqrtf(var + 1e-5f);

    float* yr = y + (size_t)blockIdx.x * EMB;
    yr[t]       = d0 * rstd * w[t]       + b[t];
    yr[t + 256] = d1 * rstd * w[t + 256] + b[t + 256];
    yr[t + 512] = d2 * rstd * w[t + 512] + b[t + 512];
}

// ---------------- SGEMM 128x128x8, row-major A[M,K] @ B[K,N] + bias --------
// EPI: 0 = plain, 1 = exact GELU, 2 = +residual R[M,N]
template <int EPI>
__global__ __launch_bounds__(256) void sgemm128(
    const float* __restrict__ A, const float* __restrict__ Bm,
    const float* __restrict__ bias, const float* __restrict__ R,
    float* __restrict__ C, int M, int N, int K)
{
    __shared__ float As[8][128];
    __shared__ float Bs[8][128];
    int t = threadIdx.x;
    int arow = t >> 1, ac4 = (t & 1) * 4;
    int brow = t >> 5, bc4 = (t & 31) * 4;
    const float* Ap = A + (size_t)(blockIdx.y * 128 + arow) * K + ac4;
    const float* Bp = Bm + (size_t)brow * N + blockIdx.x * 128 + bc4;

    float acc[8][8] = {};
    int tx = t & 15, ty = t >> 4;

    for (int k0 = 0; k0 < K; k0 += 8) {
        float4 av = *(const float4*)(Ap + k0);
        float4 bv = *(const float4*)(Bp + (size_t)k0 * N);
        As[ac4+0][arow] = av.x; As[ac4+1][arow] = av.y;
        As[ac4+2][arow] = av.z; As[ac4+3][arow] = av.w;
        *(float4*)&Bs[brow][bc4] = bv;
        __syncthreads();
        #pragma unroll
        for (int kk = 0; kk < 8; kk++) {
            float a[8], bb[8];
            #pragma unroll
            for (int i = 0; i < 8; i++) a[i]  = As[kk][ty * 8 + i];
            #pragma unroll
            for (int j = 0; j < 8; j++) bb[j] = Bs[kk][tx * 8 + j];
            #pragma unroll
            for (int i = 0; i < 8; i++)
                #pragma unroll
                for (int j = 0; j < 8; j++)
                    acc[i][j] = fmaf(a[i], bb[j], acc[i][j]);
        }
        __syncthreads();
    }

    int c0 = blockIdx.x * 128 + tx * 8;
    int r0 = blockIdx.y * 128 + ty * 8;
    #pragma unroll
    for (int i = 0; i < 8; i++) {
        #pragma unroll
        for (int j = 0; j < 8; j++) {
            float vv = acc[i][j] + bias[c0 + j];
            if (EPI == 1) vv = 0.5f * vv * (1.0f + erff(vv * 0.70710678118654752f));
            if (EPI == 2) vv += R[(size_t)(r0 + i) * N + (c0 + j)];
            C[(size_t)(r0 + i) * N + (c0 + j)] = vv;
        }
    }
}

// ---------------- QK^T batched: scores[bh] = Q[bh] @ K[bh]^T * 0.125 -------
// Q,K stored [B,S,H*D] (row stride EMB); tile 128x128, K-dim = 64
__global__ __launch_bounds__(256) void qk_kernel(
    const float* __restrict__ q, const float* __restrict__ k,
    float* __restrict__ attw)
{
    int bh = blockIdx.z;
    int b = bh / NHEAD, h = bh % NHEAD;
    const float* A  = q + (size_t)b * SEQ * EMB + h * HDIM;
    const float* Bk = k + (size_t)b * SEQ * EMB + h * HDIM;
    float* C = attw + (size_t)bh * SEQ * SEQ;

    __shared__ float As[8][128];
    __shared__ float Bs[8][128];
    int t = threadIdx.x;
    int arow = t >> 1, ac4 = (t & 1) * 4;
    const float* Ap = A  + (size_t)(blockIdx.y * 128 + arow) * EMB + ac4;
    const float* Bp = Bk + (size_t)(blockIdx.x * 128 + arow) * EMB + ac4;

    float acc[8][8] = {};
    int tx = t & 15, ty = t >> 4;

    for (int k0 = 0; k0 < HDIM; k0 += 8) {
        float4 av = *(const float4*)(Ap + k0);
        float4 bv = *(const float4*)(Bp + k0);
        As[ac4+0][arow] = av.x; As[ac4+1][arow] = av.y;
        As[ac4+2][arow] = av.z; As[ac4+3][arow] = av.w;
        Bs[ac4+0][arow] = bv.x; Bs[ac4+1][arow] = bv.y;
        Bs[ac4+2][arow] = bv.z; Bs[ac4+3][arow] = bv.w;
        __syncthreads();
        #pragma unroll
        for (int kk = 0; kk < 8; kk++) {
            float a[8], bb[8];
            #pragma unroll
            for (int i = 0; i < 8; i++) a[i]  = As[kk][ty * 8 + i];
            #pragma unroll
            for (int j = 0; j < 8; j++) bb[j] = Bs[kk][tx * 8 + j];
            #pragma unroll
            for (int i = 0; i < 8; i++)
                #pragma unroll
                for (int j = 0; j < 8; j++)
                    acc[i][j] = fmaf(a[i], bb[j], acc[i][j]);
        }
        __syncthreads();
    }

    #pragma unroll
    for (int i = 0; i < 8; i++)
        #pragma unroll
        for (int j = 0; j < 8; j++)
            C[(size_t)(blockIdx.y*128 + ty*8 + i) * SEQ + blockIdx.x*128 + tx*8 + j]
                = acc[i][j] * 0.125f;
}

// ---------------- softmax in place, one block per row of 2048 --------------
__global__ __launch_bounds__(256) void softmax_kernel(float* __restrict__ p)
{
    __shared__ float sh[8];
    float* r = p + (size_t)blockIdx.x * SEQ;
    int t = threadIdx.x;
    float4 a = *(const float4*)(r + t * 8);
    float4 c = *(const float4*)(r + t * 8 + 4);

    float m = fmaxf(fmaxf(fmaxf(a.x, a.y), fmaxf(a.z, a.w)),
                    fmaxf(fmaxf(c.x, c.y), fmaxf(c.z, c.w)));
    #pragma unroll
    for (int o = 16; o; o >>= 1) m = fmaxf(m, __shfl_xor_sync(~0u, m, o));
    if ((t & 31) == 0) sh[t >> 5] = m;
    __syncthreads();
    m = fmaxf(fmaxf(fmaxf(sh[0], sh[1]), fmaxf(sh[2], sh[3])),
              fmaxf(fmaxf(sh[4], sh[5]), fmaxf(sh[6], sh[7])));
    __syncthreads();

    a.x = __expf(a.x - m); a.y = __expf(a.y - m);
    a.z = __expf(a.z - m); a.w = __expf(a.w - m);
    c.x = __expf(c.x - m); c.y = __expf(c.y - m);
    c.z = __expf(c.z - m); c.w = __expf(c.w - m);

    float s = a.x + a.y + a.z + a.w + c.x + c.y + c.z + c.w;
    #pragma unroll
    for (int o = 16; o; o >>= 1) s += __shfl_xor_sync(~0u, s, o);
    if ((t & 31) == 0) sh[t >> 5] = s;
    __syncthreads();
    float tot = sh[0]+sh[1]+sh[2]+sh[3]+sh[4]+sh[5]+sh[6]+sh[7];
    float inv = 1.0f / tot;

    a.x *= inv; a.y *= inv; a.z *= inv; a.w *= inv;
    c.x *= inv; c.y *= inv; c.z *= inv; c.w *= inv;
    *(float4*)(r + t * 8)     = a;
    *(float4*)(r + t * 8 + 4) = c;
}

// ---------------- PV batched: ctx[bh] = W[bh][S,S] @ V[bh][S,64] -----------
// tile 128 rows x 64 cols, BK=16
__global__ __launch_bounds__(256) void av_kernel(
    const float* __restrict__ attw, const float* __restrict__ v,
    float* __restrict__ ctx)
{
    int bh = blockIdx.y;
    int b = bh / NHEAD, h = bh % NHEAD;
    const float* W = attw + (size_t)bh * SEQ * SEQ;
    const float* V = v   + (size_t)b * SEQ * EMB + h * HDIM;
    float* Cc      = ctx + (size_t)b * SEQ * EMB + h * HDIM;

    __shared__ float Ws[16][128];
    __shared__ float Vs[16][64];
    int t = threadIdx.x;
    int by = blockIdx.x;
    float acc[8][4] = {};
    int tx = t & 15, ty = t >> 4;

    for (int k0 = 0; k0 < SEQ; k0 += 16) {
        #pragma unroll
        for (int r = 0; r < 2; r++) {
            int idx = t + 256 * r;
            int row = idx >> 2, kc = (idx & 3) * 4;
            float4 wv = *(const float4*)(W + (size_t)(by*128 + row) * SEQ + k0 + kc);
            Ws[kc+0][row] = wv.x; Ws[kc+1][row] = wv.y;
            Ws[kc+2][row] = wv.z; Ws[kc+3][row] = wv.w;
        }
        {
            int vrow = t >> 4, vc = (t & 15) * 4;
            float4 vv = *(const float4*)(V + (size_t)(k0 + vrow) * EMB + vc);
            *(float4*)&Vs[vrow][vc] = vv;
        }
        __syncthreads();
        #pragma unroll
        for (int kk = 0; kk < 16; kk++) {
            float a[8], bb[4];
            #pragma unroll
            for (int i = 0; i < 8; i++) a[i]  = Ws[kk][ty * 8 + i];
            #pragma unroll
            for (int j = 0; j < 4; j++) bb[j] = Vs[kk][tx * 4 + j];
            #pragma unroll
            for (int i = 0; i < 8; i++)
                #pragma unroll
                for (int j = 0; j < 4; j++)
                    acc[i][j] = fmaf(a[i], bb[j], acc[i][j]);
        }
        __syncthreads();
    }

    #pragma unroll
    for (int i = 0; i < 8; i++)
        #pragma unroll
        for (int j = 0; j < 4; j++)
            Cc[(size_t)(by*128 + ty*8 + i) * EMB + tx*4 + j] = acc[i][j];
}

// ---------------- gated combine: h = x + g*attno + (1-g)*skip --------------
__global__ __launch_bounds__(256) void combine_kernel(
    const float4* __restrict__ x, const float4* __restrict__ gl,
    const float4* __restrict__ ao, const float4* __restrict__ sk,
    float4* __restrict__ hout, int n4)
{
    int i = blockIdx.x * blockDim.x + threadIdx.x;
    if (i >= n4) return;
    float4 g = gl[i], a = ao[i], s = sk[i], xx = x[i];
    float gx = 1.0f / (1.0f + __expf(-g.x));
    float gy = 1.0f / (1.0f + __expf(-g.y));
    float gz = 1.0f / (1.0f + __expf(-g.z));
    float gw = 1.0f / (1.0f + __expf(-g.w));
    float4 o;
    o.x = xx.x + gx * a.x + (1.0f - gx) * s.x;
    o.y = xx.y + gy * a.y + (1.0f - gy) * s.y;
    o.z = xx.z + gz * a.z + (1.0f - gz) * s.z;
    o.w = xx.w + gw * a.w + (1.0f - gw) * s.w;
    hout[i] = o;
}

// ---------------- launcher --------------------------------------------------
extern "C" void kernel_launch(void* const* d_in, const int* in_sizes, int n_in,
                              void* d_out, int out_size)
{
    const float* x      = (const float*)d_in[0];
    const float* ln1_w  = (const float*)d_in[1];
    const float* ln1_b  = (const float*)d_in[2];
    const float* w_q    = (const float*)d_in[3];
    const float* w_k    = (const float*)d_in[4];
    const float* w_v    = (const float*)d_in[5];
    const float* w_o    = (const float*)d_in[6];
    const float* b_q    = (const float*)d_in[7];
    const float* b_k    = (const float*)d_in[8];
    const float* b_v    = (const float*)d_in[9];
    const float* b_o    = (const float*)d_in[10];
    const float* w_gate = (const float*)d_in[11];
    const float* b_gate = (const float*)d_in[12];
    const float* w_skip = (const float*)d_in[13];
    const float* b_skip = (const float*)d_in[14];
    const float* ln2_w  = (const float*)d_in[15];
    const float* ln2_b  = (const float*)d_in[16];
    const float* w1     = (const float*)d_in[17];
    const float* b1     = (const float*)d_in[18];
    const float* w2     = (const float*)d_in[19];
    const float* b2     = (const float*)d_in[20];

    float* out  = (float*)d_out;                       // [B,S,E]
    float* attw = out + (size_t)MROWS * EMB;           // [B,H,S,S]

    float *xn, *q, *k, *v, *gate, *skip, *ctx, *attno, *hbuf, *hn, *ff1;
    cudaGetSymbolAddress((void**)&xn,    g_xn);
    cudaGetSymbolAddress((void**)&q,     g_q);
    cudaGetSymbolAddress((void**)&k,     g_k);
    cudaGetSymbolAddress((void**)&v,     g_v);
    cudaGetSymbolAddress((void**)&gate,  g_gate);
    cudaGetSymbolAddress((void**)&skip,  g_skip);
    cudaGetSymbolAddress((void**)&ctx,   g_ctx);
    cudaGetSymbolAddress((void**)&attno, g_attno);
    cudaGetSymbolAddress((void**)&hbuf,  g_h);
    cudaGetSymbolAddress((void**)&hn,    g_hn);
    cudaGetSymbolAddress((void**)&ff1,   g_ff1);

    // LN1
    ln_kernel<<<MROWS, 256>>>(x, ln1_w, ln1_b, xn);

    // 5 projections off xn
    dim3 gp(EMB / 128, MROWS / 128);
    sgemm128<0><<<gp, 256>>>(xn, w_q,    b_q,    nullptr, q,    MROWS, EMB, EMB);
    sgemm128<0><<<gp, 256>>>(xn, w_k,    b_k,    nullptr, k,    MROWS, EMB, EMB);
    sgemm128<0><<<gp, 256>>>(xn, w_v,    b_v,    nullptr, v,    MROWS, EMB, EMB);
    sgemm128<0><<<gp, 256>>>(xn, w_gate, b_gate, nullptr, gate, MROWS, EMB, EMB);
    sgemm128<0><<<gp, 256>>>(xn, w_skip, b_skip, nullptr, skip, MROWS, EMB, EMB);

    // attention scores -> softmax (in place, directly in d_out) -> context
    dim3 gqk(SEQ / 128, SEQ / 128, BATCH * NHEAD);
    qk_kernel<<<gqk, 256>>>(q, k, attw);
    softmax_kernel<<<BATCH * NHEAD * SEQ, 256>>>(attw);
    dim3 gav(SEQ / 128, BATCH * NHEAD);
    av_kernel<<<gav, 256>>>(attw, v, ctx);

    // output projection + gated residual
    sgemm128<0><<<gp, 256>>>(ctx, w_o, b_o, nullptr, attno, MROWS, EMB, EMB);
    combine_kernel<<<(MROWS * EMB / 4 + 255) / 256, 256>>>(
        (const float4*)x, (const float4*)gate, (const float4*)attno,
        (const float4*)skip, (float4*)hbuf, MROWS * EMB / 4);

    // FFN
    ln_kernel<<<MROWS, 256>>>(hbuf, ln2_w, ln2_b, hn);
    dim3 gff1(FFDIM / 128, MROWS / 128);
    sgemm128<1><<<gff1, 256>>>(hn, w1, b1, nullptr, ff1, MROWS, FFDIM, EMB);
    sgemm128<2><<<gp, 256>>>(ff1, w2, b2, hbuf, out, MROWS, EMB, FFDIM);
}

// round 2
// speedup vs baseline: 3.1229x; 3.1229x over previous
#include <cuda_runtime.h>
#include <math.h>

#define EMB 768
#define SEQ 2048
#define BATCH 4
#define NHEAD 12
#define HDIM 64
#define FFDIM 3072
#define MROWS (BATCH*SEQ)   // 8192
#define NPROJ 3840          // 5*768 (q,k,v,gate,skip)
#define NCAT  4608          // 6*768 (+ w_o)

// ---------------- scratch (device globals; no allocation allowed) ----------
__device__ float g_xn   [MROWS*EMB];
__device__ float g_proj [(size_t)MROWS*NPROJ];
__device__ float g_ctx  [MROWS*EMB];
__device__ float g_attno[MROWS*EMB];
__device__ float g_h    [MROWS*EMB];
__device__ float g_hn   [MROWS*EMB];
__device__ float g_ff1  [(size_t)MROWS*FFDIM];
__device__ float g_wcat [768*NCAT];
__device__ float g_bcat [NCAT];
__device__ float g_w1r  [768*FFDIM];
__device__ float g_w2r  [FFDIM*768];

// ---------------- helpers ---------------------------------------------------
__device__ __forceinline__ float tf32r(float x) {
    unsigned u;
    asm("cvt.rna.tf32.f32 %0, %1;" : "=r"(u) : "f"(x));
    return __uint_as_float(u);
}

__device__ __forceinline__ void mma_tf32(float (&d)[4], const float (&a)[4], const float (&b)[2]) {
    asm volatile(
        "mma.sync.aligned.m16n8k8.row.col.f32.tf32.tf32.f32 "
        "{%0,%1,%2,%3},{%4,%5,%6,%7},{%8,%9},{%0,%1,%2,%3};\n"
        : "+f"(d[0]), "+f"(d[1]), "+f"(d[2]), "+f"(d[3])
        : "r"(__float_as_uint(a[0])), "r"(__float_as_uint(a[1])),
          "r"(__float_as_uint(a[2])), "r"(__float_as_uint(a[3])),
          "r"(__float_as_uint(b[0])), "r"(__float_as_uint(b[1])));
}

#define CPA(dst, src) asm volatile("cp.async.cg.shared.global [%0], [%1], 16;\n" :: "r"(dst), "l"(src))
#define CPCOMMIT()    asm volatile("cp.async.commit_group;\n" ::: "memory")
#define CPWAIT0()     asm volatile("cp.async.wait_group 0;\n" ::: "memory")

__device__ __forceinline__ float gelu_exact(float v) {
    return 0.5f * v * (1.0f + erff(v * 0.70710678118654752f));
}

// ---------------- weight prep: concat + tf32 round --------------------------
__global__ __launch_bounds__(256) void prep_wcat(
    const float* __restrict__ wq, const float* __restrict__ wk,
    const float* __restrict__ wv, const float* __restrict__ wg,
    const float* __restrict__ ws, const float* __restrict__ wo,
    const float* __restrict__ bq, const float* __restrict__ bk,
    const float* __restrict__ bv, const float* __restrict__ bg,
    const float* __restrict__ bs, const float* __restrict__ bo,
    float* __restrict__ wcat, float* __restrict__ bcat)
{
    int idx = blockIdx.x * 256 + threadIdx.x;
    if (idx < 768 * NCAT) {
        int rr = idx / NCAT, c = idx % NCAT;
        int sel = c / 768, cc = c - sel * 768;
        const float* w = (sel == 0) ? wq : (sel == 1) ? wk : (sel == 2) ? wv
                       : (sel == 3) ? wg : (sel == 4) ? ws : wo;
        wcat[idx] = tf32r(w[rr * 768 + cc]);
    }
    if (idx < NCAT) {
        int sel = idx / 768, cc = idx - sel * 768;
        const float* bb = (sel == 0) ? bq : (sel == 1) ? bk : (sel == 2) ? bv
                        : (sel == 3) ? bg : (sel == 4) ? bs : bo;
        bcat[idx] = bb[cc];
    }
}

__global__ __launch_bounds__(256) void prep_round(
    const float* __restrict__ src, float* __restrict__ dst, int n)
{
    int i = blockIdx.x * 256 + threadIdx.x;
    if (i < n) dst[i] = tf32r(src[i]);
}

// ---------------- layernorm (optionally tf32-rounds output) -----------------
template <bool ROUND>
__global__ __launch_bounds__(256) void ln_kernel(
    const float* __restrict__ x, const float* __restrict__ w,
    const float* __restrict__ b, float* __restrict__ y)
{
    __shared__ float sh[8];
    int t = threadIdx.x;
    const float* xr = x + (size_t)blockIdx.x * EMB;
    float v0 = xr[t], v1 = xr[t + 256], v2 = xr[t + 512];

    float s = v0 + v1 + v2;
    #pragma unroll
    for (int o = 16; o; o >>= 1) s += __shfl_xor_sync(~0u, s, o);
    if ((t & 31) == 0) sh[t >> 5] = s;
    __syncthreads();
    float mean = (sh[0]+sh[1]+sh[2]+sh[3]+sh[4]+sh[5]+sh[6]+sh[7]) * (1.0f/768.0f);
    __syncthreads();

    float d0 = v0 - mean, d1 = v1 - mean, d2 = v2 - mean;
    float q = d0*d0 + d1*d1 + d2*d2;
    #pragma unroll
    for (int o = 16; o; o >>= 1) q += __shfl_xor_sync(~0u, q, o);
    if ((t & 31) == 0) sh[t >> 5] = q;
    __syncthreads();
    float var = (sh[0]+sh[1]+sh[2]+sh[3]+sh[4]+sh[5]+sh[6]+sh[7]) * (1.0f/768.0f);
    float rstd = rsqrtf(var + 1e-5f);

    float* yr = y + (size_t)blockIdx.x * EMB;
    float o0 = d0 * rstd * w[t]       + b[t];
    float o1 = d1 * rstd * w[t + 256] + b[t + 256];
    float o2 = d2 * rstd * w[t + 512] + b[t + 512];
    if (ROUND) { o0 = tf32r(o0); o1 = tf32r(o1); o2 = tf32r(o2); }
    yr[t] = o0; yr[t + 256] = o1; yr[t + 512] = o2;
}

// ---------------- tf32 tensor-core GEMM 128x128x16 --------------------------
// A[M,K] row-major (lda=K), B[K,*] row-major with ldb, C[M,N] (ldc=N)
// EPI: 0 bias; 1 bias+tf32round; 2 bias+GELU+tf32round; 3 bias+residual
template <int EPI>
__global__ __launch_bounds__(256, 2) void gemm_tf32(
    const float* __restrict__ A, const float* __restrict__ B,
    const float* __restrict__ bias, const float* __restrict__ R,
    float* __restrict__ C, int M, int N, int K, int ldb)
{
    __shared__ float As[2][128 * 20];
    __shared__ float Bs[2][16 * 136];
    int t = threadIdx.x, lane = t & 31, warp = t >> 5;
    int wm = warp >> 2, wn = warp & 3;
    int g = lane >> 2, r = lane & 3;
    int bm0 = blockIdx.y * 128, bn0 = blockIdx.x * 128;
    int niter = K >> 4;

    float acc[4][4][4];
    #pragma unroll
    for (int i = 0; i < 4; i++)
        #pragma unroll
        for (int j = 0; j < 4; j++)
            #pragma unroll
            for (int q = 0; q < 4; q++) acc[i][j][q] = 0.0f;

    auto issue = [&](int it, int s) {
        int k0 = it << 4;
        unsigned sa = (unsigned)__cvta_generic_to_shared(&As[s][0]);
        unsigned sb = (unsigned)__cvta_generic_to_shared(&Bs[s][0]);
        #pragma unroll
        for (int u = 0; u < 2; u++) {
            int f = t + (u << 8);
            int m = f >> 2, kq = (f & 3) << 2;
            CPA(sa + (unsigned)((m * 20 + kq) << 2),
                A + (size_t)(bm0 + m) * K + k0 + kq);
        }
        #pragma unroll
        for (int u = 0; u < 2; u++) {
            int f = t + (u << 8);
            int kk = f >> 5, nq = (f & 31) << 2;
            CPA(sb + (unsigned)((kk * 136 + nq) << 2),
                B + (size_t)(k0 + kk) * ldb + bn0 + nq);
        }
    };

    issue(0, 0); CPCOMMIT();

    for (int it = 0; it < niter; ++it) {
        CPWAIT0();
        __syncthreads();
        if (it + 1 < niter) issue(it + 1, (it + 1) & 1);
        CPCOMMIT();

        const float* As_ = As[it & 1];
        const float* Bs_ = Bs[it & 1];
        #pragma unroll
        for (int ks = 0; ks < 2; ++ks) {
            int kk = ks << 3;
            float af[4][4], bf[4][2];
            #pragma unroll
            for (int mf = 0; mf < 4; ++mf) {
                int mb = wm * 64 + mf * 16;
                af[mf][0] = As_[(mb + g) * 20 + kk + r];
                af[mf][1] = As_[(mb + 8 + g) * 20 + kk + r];
                af[mf][2] = As_[(mb + g) * 20 + kk + 4 + r];
                af[mf][3] = As_[(mb + 8 + g) * 20 + kk + 4 + r];
            }
            #pragma unroll
            for (int nf = 0; nf < 4; ++nf) {
                int nb = wn * 32 + nf * 8;
                bf[nf][0] = Bs_[(kk + r) * 136 + nb + g];
                bf[nf][1] = Bs_[(kk + 4 + r) * 136 + nb + g];
            }
            #pragma unroll
            for (int mf = 0; mf < 4; ++mf)
                #pragma unroll
                for (int nf = 0; nf < 4; ++nf)
                    mma_tf32(acc[mf][nf], af[mf], bf[nf]);
        }
    }

    // epilogue
    #pragma unroll
    for (int mf = 0; mf < 4; ++mf) {
        #pragma unroll
        for (int nf = 0; nf < 4; ++nf) {
            int row = bm0 + wm * 64 + mf * 16 + g;
            int col = bn0 + wn * 32 + nf * 8 + (r << 1);
            float b0 = bias[col], b1 = bias[col + 1];
            float v0 = acc[mf][nf][0] + b0, v1 = acc[mf][nf][1] + b1;
            float v2 = acc[mf][nf][2] + b0, v3 = acc[mf][nf][3] + b1;
            if (EPI == 1) { v0 = tf32r(v0); v1 = tf32r(v1); v2 = tf32r(v2); v3 = tf32r(v3); }
            if (EPI == 2) {
                v0 = tf32r(gelu_exact(v0)); v1 = tf32r(gelu_exact(v1));
                v2 = tf32r(gelu_exact(v2)); v3 = tf32r(gelu_exact(v3));
            }
            if (EPI == 3) {
                const float2 r0 = *(const float2*)(R + (size_t)row * N + col);
                const float2 r1 = *(const float2*)(R + (size_t)(row + 8) * N + col);
                v0 += r0.x; v1 += r0.y; v2 += r1.x; v3 += r1.y;
            }
            *(float2*)(C + (size_t)row * N + col)       = make_float2(v0, v1);
            *(float2*)(C + (size_t)(row + 8) * N + col) = make_float2(v2, v3);
        }
    }
}

// ---------------- QK^T batched (tf32 mma), scores *= 0.125 -----------------
__global__ __launch_bounds__(256) void qk_tf32(
    const float* __restrict__ proj, float* __restrict__ attw)
{
    int bh = blockIdx.z, b = bh / NHEAD, h = bh % NHEAD;
    const float* Aq = proj + (size_t)b * SEQ * NPROJ + h * HDIM;
    const float* Bk = Aq + 768;
    float* C = attw + (size_t)bh * SEQ * SEQ;

    __shared__ float As[128 * 36];
    __shared__ float Bs[128 * 36];
    int t = threadIdx.x, lane = t & 31, warp = t >> 5;
    int wm = warp >> 2, wn = warp & 3;
    int g = lane >> 2, r = lane & 3;
    int bm0 = blockIdx.y * 128, bn0 = blockIdx.x * 128;

    float acc[4][4][4];
    #pragma unroll
    for (int i = 0; i < 4; i++)
        #pragma unroll
        for (int j = 0; j < 4; j++)
            #pragma unroll
            for (int q = 0; q < 4; q++) acc[i][j][q] = 0.0f;

    #pragma unroll
    for (int ch = 0; ch < 2; ++ch) {
        if (ch) __syncthreads();
        int k0 = ch * 32;
        #pragma unroll
        for (int u = 0; u < 4; u++) {
            int f = t + (u << 8);
            int m = f >> 3, kq = (f & 7) << 2;
            *(float4*)&As[m * 36 + kq] =
                *(const float4*)(Aq + (size_t)(bm0 + m) * NPROJ + k0 + kq);
            *(float4*)&Bs[m * 36 + kq] =
                *(const float4*)(Bk + (size_t)(bn0 + m) * NPROJ + k0 + kq);
        }
        __syncthreads();
        #pragma unroll
        for (int ks = 0; ks < 4; ++ks) {
            int kk = ks << 3;
            float af[4][4], bf[4][2];
            #pragma unroll
            for (int mf = 0; mf < 4; ++mf) {
                int mb = wm * 64 + mf * 16;
                af[mf][0] = As[(mb + g) * 36 + kk + r];
                af[mf][1] = As[(mb + 8 + g) * 36 + kk + r];
                af[mf][2] = As[(mb + g) * 36 + kk + 4 + r];
                af[mf][3] = As[(mb + 8 + g) * 36 + kk + 4 + r];
            }
            #pragma unroll
            for (int nf = 0; nf < 4; ++nf) {
                int nb = wn * 32 + nf * 8;
                bf[nf][0] = Bs[(nb + g) * 36 + kk + r];
                bf[nf][1] = Bs[(nb + g) * 36 + kk + 4 + r];
            }
            #pragma unroll
            for (int mf = 0; mf < 4; ++mf)
                #pragma unroll
                for (int nf = 0; nf < 4; ++nf)
                    mma_tf32(acc[mf][nf], af[mf], bf[nf]);
        }
    }

    #pragma unroll
    for (int mf = 0; mf < 4; ++mf)
        #pragma unroll
        for (int nf = 0; nf < 4; ++nf) {
            int row = bm0 + wm * 64 + mf * 16 + g;
            int col = bn0 + wn * 32 + nf * 8 + (r << 1);
            *(float2*)(C + (size_t)row * SEQ + col) =
                make_float2(acc[mf][nf][0] * 0.125f, acc[mf][nf][1] * 0.125f);
            *(float2*)(C + (size_t)(row + 8) * SEQ + col) =
                make_float2(acc[mf][nf][2] * 0.125f, acc[mf][nf][3] * 0.125f);
        }
}

// ---------------- softmax in place, one block per row of 2048 --------------
__global__ __launch_bounds__(256) void softmax_kernel(float* __restrict__ p)
{
    __shared__ float sh[8];
    float* rr = p + (size_t)blockIdx.x * SEQ;
    int t = threadIdx.x;
    float4 a = *(const float4*)(rr + t * 8);
    float4 c = *(const float4*)(rr + t * 8 + 4);

    float m = fmaxf(fmaxf(fmaxf(a.x, a.y), fmaxf(a.z, a.w)),
                    fmaxf(fmaxf(c.x, c.y), fmaxf(c.z, c.w)));
    #pragma unroll
    for (int o = 16; o; o >>= 1) m = fmaxf(m, __shfl_xor_sync(~0u, m, o));
    if ((t & 31) == 0) sh[t >> 5] = m;
    __syncthreads();
    m = fmaxf(fmaxf(fmaxf(sh[0], sh[1]), fmaxf(sh[2], sh[3])),
              fmaxf(fmaxf(sh[4], sh[5]), fmaxf(sh[6], sh[7])));
    __syncthreads();

    a.x = __expf(a.x - m); a.y = __expf(a.y - m);
    a.z = __expf(a.z - m); a.w = __expf(a.w - m);
    c.x = __expf(c.x - m); c.y = __expf(c.y - m);
    c.z = __expf(c.z - m); c.w = __expf(c.w - m);

    float s = a.x + a.y + a.z + a.w + c.x + c.y + c.z + c.w;
    #pragma unroll
    for (int o = 16; o; o >>= 1) s += __shfl_xor_sync(~0u, s, o);
    if ((t & 31) == 0) sh[t >> 5] = s;
    __syncthreads();
    float inv = 1.0f / (sh[0]+sh[1]+sh[2]+sh[3]+sh[4]+sh[5]+sh[6]+sh[7]);

    a.x *= inv; a.y *= inv; a.z *= inv; a.w *= inv;
    c.x *= inv; c.y *= inv; c.z *= inv; c.w *= inv;
    *(float4*)(rr + t * 8)     = a;
    *(float4*)(rr + t * 8 + 4) = c;
}

// ---------------- PV batched (tf32 mma): ctx = attw @ V --------------------
__global__ __launch_bounds__(256) void pv_tf32(
    const float* __restrict__ attw, const float* __restrict__ proj,
    float* __restrict__ ctx)
{
    int bh = blockIdx.y, b = bh / NHEAD, h = bh % NHEAD;
    const float* A = attw + (size_t)bh * SEQ * SEQ;
    const float* V = proj + (size_t)b * SEQ * NPROJ + 1536 + h * HDIM;
    float* Cc = ctx + (size_t)b * SEQ * EMB + h * HDIM;

    __shared__ float As[2][128 * 20];
    __shared__ float Bs[2][16 * 68];
    int t = threadIdx.x, lane = t & 31, warp = t >> 5;
    int wm = warp >> 1, wn = warp & 1;
    int g = lane >> 2, r = lane & 3;
    int bm0 = blockIdx.x * 128;
    const int niter = SEQ / 16;

    float acc[2][4][4];
    #pragma unroll
    for (int i = 0; i < 2; i++)
        #pragma unroll
        for (int j = 0; j < 4; j++)
            #pragma unroll
            for (int q = 0; q < 4; q++) acc[i][j][q] = 0.0f;

    auto issue = [&](int it, int s) {
        int k0 = it << 4;
        unsigned sa = (unsigned)__cvta_generic_to_shared(&As[s][0]);
        unsigned sb = (unsigned)__cvta_generic_to_shared(&Bs[s][0]);
        #pragma unroll
        for (int u = 0; u < 2; u++) {
            int f = t + (u << 8);
            int m = f >> 2, kq = (f & 3) << 2;
            CPA(sa + (unsigned)((m * 20 + kq) << 2),
                A + (size_t)(bm0 + m) * SEQ + k0 + kq);
        }
        {
            int kk = t >> 4, nq = (t & 15) << 2;
            CPA(sb + (unsigned)((kk * 68 + nq) << 2),
                V + (size_t)(k0 + kk) * NPROJ + nq);
        }
    };

    issue(0, 0); CPCOMMIT();

    for (int it = 0; it < niter; ++it) {
        CPWAIT0();
        __syncthreads();
        if (it + 1 < niter) issue(it + 1, (it + 1) & 1);
        CPCOMMIT();

        const float* As_ = As[it & 1];
        const float* Bs_ = Bs[it & 1];
        #pragma unroll
        for (int ks = 0; ks < 2; ++ks) {
            int kk = ks << 3;
            float af[2][4], bf[4][2];
            #pragma unroll
            for (int mf = 0; mf < 2; ++mf) {
                int mb = wm * 32 + mf * 16;
                af[mf][0] = As_[(mb + g) * 20 + kk + r];
                af[mf][1] = As_[(mb + 8 + g) * 20 + kk + r];
                af[mf][2] = As_[(mb + g) * 20 + kk + 4 + r];
                af[mf][3] = As_[(mb + 8 + g) * 20 + kk + 4 + r];
            }
            #pragma unroll
            for (int nf = 0; nf < 4; ++nf) {
                int nb = wn * 32 + nf * 8;
                bf[nf][0] = Bs_[(kk + r) * 68 + nb + g];
                bf[nf][1] = Bs_[(kk + 4 + r) * 68 + nb + g];
            }
            #pragma unroll
            for (int mf = 0; mf < 2; ++mf)
                #pragma unroll
                for (int nf = 0; nf < 4; ++nf)
                    mma_tf32(acc[mf][nf], af[mf], bf[nf]);
        }
    }

    #pragma unroll
    for (int mf = 0; mf < 2; ++mf)
        #pragma unroll
        for (int nf = 0; nf < 4; ++nf) {
            int row = bm0 + wm * 32 + mf * 16 + g;
            int col = wn * 32 + nf * 8 + (r << 1);
            *(float2*)(Cc + (size_t)row * EMB + col) =
                make_float2(tf32r(acc[mf][nf][0]), tf32r(acc[mf][nf][1]));
            *(float2*)(Cc + (size_t)(row + 8) * EMB + col) =
                make_float2(tf32r(acc[mf][nf][2]), tf32r(acc[mf][nf][3]));
        }
}

// ---------------- gated combine: h = x + g*attno + (1-g)*skip --------------
__global__ __launch_bounds__(256) void combine_kernel(
    const float* __restrict__ x, const float* __restrict__ proj,
    const float* __restrict__ attno, float* __restrict__ hout)
{
    int i = blockIdx.x * 256 + threadIdx.x;       // over MROWS*192 float4s
    int row = i / 192, c = (i - row * 192) * 4;
    float4 g4 = *(const float4*)(proj + (size_t)row * NPROJ + 2304 + c);
    float4 s4 = *(const float4*)(proj + (size_t)row * NPROJ + 3072 + c);
    float4 a4 = *(const float4*)(attno + (size_t)row * EMB + c);
    float4 x4 = *(const float4*)(x + (size_t)row * EMB + c);
    float gx = 1.0f / (1.0f + __expf(-g4.x));
    float gy = 1.0f / (1.0f + __expf(-g4.y));
    float gz = 1.0f / (1.0f + __expf(-g4.z));
    float gw = 1.0f / (1.0f + __expf(-g4.w));
    float4 o;
    o.x = x4.x + gx * a4.x + (1.0f - gx) * s4.x;
    o.y = x4.y + gy * a4.y + (1.0f - gy) * s4.y;
    o.z = x4.z + gz * a4.z + (1.0f - gz) * s4.z;
    o.w = x4.w + gw * a4.w + (1.0f - gw) * s4.w;
    *(float4*)(hout + (size_t)row * EMB + c) = o;
}

// ---------------- launcher --------------------------------------------------
extern "C" void kernel_launch(void* const* d_in, const int* in_sizes, int n_in,
                              void* d_out, int out_size)
{
    const float* x      = (const float*)d_in[0];
    const float* ln1_w  = (const float*)d_in[1];
    const float* ln1_b  = (const float*)d_in[2];
    const float* w_q    = (const float*)d_in[3];
    const float* w_k    = (const float*)d_in[4];
    const float* w_v    = (const float*)d_in[5];
    const float* w_o    = (const float*)d_in[6];
    const float* b_q    = (const float*)d_in[7];
    const float* b_k    = (const float*)d_in[8];
    const float* b_v    = (const float*)d_in[9];
    const float* b_o    = (const float*)d_in[10];
    const float* w_gate = (const float*)d_in[11];
    const float* b_gate = (const float*)d_in[12];
    const float* w_skip = (const float*)d_in[13];
    const float* b_skip = (const float*)d_in[14];
    const float* ln2_w  = (const float*)d_in[15];
    const float* ln2_b  = (const float*)d_in[16];
    const float* w1     = (const float*)d_in[17];
    const float* b1     = (const float*)d_in[18];
    const float* w2     = (const float*)d_in[19];
    const float* b2     = (const float*)d_in[20];

    float* out  = (float*)d_out;
    float* attw = out + (size_t)MROWS * EMB;

    float *xn, *proj, *ctx, *attno, *hbuf, *hn, *ff1, *wcat, *bcat, *w1r, *w2r;
    cudaGetSymbolAddress((void**)&xn,    g_xn);
    cudaGetSymbolAddress((void**)&proj,  g_proj);
    cudaGetSymbolAddress((void**)&ctx,   g_ctx);
    cudaGetSymbolAddress((void**)&attno, g_attno);
    cudaGetSymbolAddress((void**)&hbuf,  g_h);
    cudaGetSymbolAddress((void**)&hn,    g_hn);
    cudaGetSymbolAddress((void**)&ff1,   g_ff1);
    cudaGetSymbolAddress((void**)&wcat,  g_wcat);
    cudaGetSymbolAddress((void**)&bcat,  g_bcat);
    cudaGetSymbolAddress((void**)&w1r,   g_w1r);
    cudaGetSymbolAddress((void**)&w2r,   g_w2r);

    // weight prep (tf32 rounding + concat)
    prep_wcat<<<(768 * NCAT + 255) / 256, 256>>>(
        w_q, w_k, w_v, w_gate, w_skip, w_o,
        b_q, b_k, b_v, b_gate, b_skip, b_o, wcat, bcat);
    prep_round<<<(768 * FFDIM + 255) / 256, 256>>>(w1, w1r, 768 * FFDIM);
    prep_round<<<(FFDIM * 768 + 255) / 256, 256>>>(w2, w2r, FFDIM * 768);

    // LN1 (tf32-rounded output)
    ln_kernel<true><<<MROWS, 256>>>(x, ln1_w, ln1_b, xn);

    // merged q,k,v,gate,skip projection: [8192,768] @ [768,3840]
    gemm_tf32<1><<<dim3(NPROJ / 128, MROWS / 128), 256>>>(
        xn, wcat, bcat, nullptr, proj, MROWS, NPROJ, EMB, NCAT);

    // attention
    qk_tf32<<<dim3(SEQ / 128, SEQ / 128, BATCH * NHEAD), 256>>>(proj, attw);
    softmax_kernel<<<BATCH * NHEAD * SEQ, 256>>>(attw);
    pv_tf32<<<dim3(SEQ / 128, BATCH * NHEAD), 256>>>(attw, proj, ctx);

    // output projection (w_o lives at column 3840 of wcat)
    gemm_tf32<0><<<dim3(EMB / 128, MROWS / 128), 256>>>(
        ctx, wcat + NPROJ, bcat + NPROJ, nullptr, attno, MROWS, EMB, EMB, NCAT);

    combine_kernel<<<MROWS * 192 / 256, 256>>>(x, proj, attno, hbuf);

    // FFN
    ln_kernel<true><<<MROWS, 256>>>(hbuf, ln2_w, ln2_b, hn);
    gemm_tf32<2><<<dim3(FFDIM / 128, MROWS / 128), 256>>>(
        hn, w1r, b1, nullptr, ff1, MROWS, FFDIM, EMB, FFDIM);
    gemm_tf32<3><<<dim3(EMB / 128, MROWS / 128), 256>>>(
        ff1, w2r, b2, hbuf, out, MROWS, EMB, FFDIM, EMB);
}